// round 6
// baseline (speedup 1.0000x reference)
#include <cuda_runtime.h>
#include <math.h>

#define HH 128
#define WW 128
#define HWSZ (HH*WW)
#define NFC 64
#define BB 4

// Scratch ping-pong buffers (no allocation allowed)
__device__ float g_bufA[BB*NFC*HWSZ];
__device__ float g_bufB[BB*NFC*HWSZ];

// ---------------------------------------------------------------------------
// Tiled 3x3 conv, stride 1, pad 1.
// Tile: 32x16 spatial, 8 oc per block, 4 px per thread (x), 8-ci smem chunks.
// mode 0: lrelu -> out [B,cout,H,W]
// mode 1: ch<18 -> 15*tanh -> outOff [B,18,H,W]; ch>=18 -> sigmoid -> outMask [B,9,H,W]
// ---------------------------------------------------------------------------
__global__ __launch_bounds__(128) void conv3x3_k(
    const float* __restrict__ in0, const float* __restrict__ in1, int cin,
    const float* __restrict__ wgt, const float* __restrict__ bias,
    float* __restrict__ out, int cout, int mode,
    float* __restrict__ outOff, float* __restrict__ outMask)
{
    __shared__ float s_in[8][18][34];   // [ci][row 16+2][col 32+2]
    __shared__ float s_w[8][8][9];      // [oc][ci][k]

    const int tx = threadIdx.x;         // 0..7
    const int ty = threadIdx.y;         // 0..15
    const int tid = ty * 8 + tx;
    const int x0 = blockIdx.x * 32;
    const int y0 = blockIdx.y * 16;
    const int groups = (cout + 7) / 8;
    const int b = blockIdx.z / groups;
    const int ocBase = (blockIdx.z % groups) * 8;

    float acc[8][4];
#pragma unroll
    for (int o = 0; o < 8; o++)
#pragma unroll
        for (int p = 0; p < 4; p++) acc[o][p] = 0.f;

    for (int cb = 0; cb < cin; cb += 8) {
        __syncthreads();
        // load input tile (8 channels, 18x34 with halo, zero padded)
        for (int idx = tid; idx < 8 * 612; idx += 128) {
            int ci = idx / 612;
            int rem = idx % 612;
            int r = rem / 34;
            int c = rem % 34;
            int gy = y0 + r - 1;
            int gx = x0 + c - 1;
            int ch = cb + ci;
            const float* src = in0;
            int chl = ch;
            if (ch >= 64) { src = in1; chl = ch - 64; }
            float v = 0.f;
            if (gy >= 0 && gy < HH && gx >= 0 && gx < WW)
                v = __ldg(&src[((b * 64 + chl) * HH + gy) * WW + gx]);
            (&s_in[0][0][0])[idx] = v;
        }
        // load weights for this (oc block, ci chunk)
        for (int idx = tid; idx < 8 * 8 * 9; idx += 128) {
            int oc = idx / 72;
            int rem = idx % 72;
            int ci = rem / 9;
            int k = rem % 9;
            int gc = ocBase + oc;
            float v = 0.f;
            if (gc < cout) v = __ldg(&wgt[(gc * cin + cb + ci) * 9 + k]);
            (&s_w[0][0][0])[idx] = v;
        }
        __syncthreads();

#pragma unroll 2
        for (int ci = 0; ci < 8; ci++) {
            float v[3][6];
#pragma unroll
            for (int r = 0; r < 3; r++)
#pragma unroll
                for (int c = 0; c < 6; c++)
                    v[r][c] = s_in[ci][ty + r][tx * 4 + c];
#pragma unroll
            for (int oc = 0; oc < 8; oc++) {
#pragma unroll
                for (int kr = 0; kr < 3; kr++)
#pragma unroll
                    for (int kc = 0; kc < 3; kc++) {
                        float wv = s_w[oc][ci][kr * 3 + kc];
#pragma unroll
                        for (int p = 0; p < 4; p++)
                            acc[oc][p] = fmaf(v[kr][kc + p], wv, acc[oc][p]);
                    }
            }
        }
    }

    const int y = y0 + ty;
    const int xb = x0 + tx * 4;
#pragma unroll
    for (int oc = 0; oc < 8; oc++) {
        int gc = ocBase + oc;
        if (gc >= cout) continue;
        float bv = __ldg(&bias[gc]);
        float r[4];
#pragma unroll
        for (int p = 0; p < 4; p++) r[p] = acc[oc][p] + bv;
        if (mode == 0) {
#pragma unroll
            for (int p = 0; p < 4; p++) r[p] = (r[p] >= 0.f) ? r[p] : 0.1f * r[p];
            float4 v4 = make_float4(r[0], r[1], r[2], r[3]);
            *(float4*)&out[((b * cout + gc) * HH + y) * WW + xb] = v4;
        } else {
            if (gc < 18) {
#pragma unroll
                for (int p = 0; p < 4; p++) r[p] = 15.f * tanhf(r[p]);
                float4 v4 = make_float4(r[0], r[1], r[2], r[3]);
                *(float4*)&outOff[((b * 18 + gc) * HH + y) * WW + xb] = v4;
            } else {
#pragma unroll
                for (int p = 0; p < 4; p++) r[p] = 1.f / (1.f + expf(-r[p]));
                float4 v4 = make_float4(r[0], r[1], r[2], r[3]);
                *(float4*)&outMask[((b * 9 + (gc - 18)) * HH + y) * WW + xb] = v4;
            }
        }
    }
}

// ---------------------------------------------------------------------------
// Modulated deformable conv (DCNv2), 64->64, K=9, stride1/pad1/dil1.
// Block: (32,4) threads, each thread 4 consecutive x pixels, 16 oc per block
// (4 oc-groups in grid.y). Bilinear corner weights/indices computed once per
// tap per pixel, reused over all 64 input channels. Weights staged in smem.
// ---------------------------------------------------------------------------
__global__ __launch_bounds__(128, 4) void dcn_k(
    const float* __restrict__ xin, const float* __restrict__ off,
    const float* __restrict__ msk, const float* __restrict__ wgt,
    const float* __restrict__ bias, float* __restrict__ out)
{
    __shared__ float s_w[16 * 64 * 9];   // [oc][c][k]

    const int tx = threadIdx.x;          // 0..31
    const int ty = threadIdx.y;          // 0..3
    const int tid = ty * 32 + tx;
    const int y = blockIdx.x * 4 + ty;
    const int b = blockIdx.y >> 2;
    const int ocBase = (blockIdx.y & 3) * 16;

    for (int idx = tid; idx < 16 * 64 * 9; idx += 128) {
        int oc = idx / 576;
        int rem = idx % 576;
        s_w[idx] = __ldg(&wgt[(ocBase + oc) * 576 + rem]);
    }
    __syncthreads();

    const int xb = tx * 4;
    float acc[16][4];
#pragma unroll
    for (int o = 0; o < 16; o++)
#pragma unroll
        for (int p = 0; p < 4; p++) acc[o][p] = 0.f;

    const float* xbase = xin + (size_t)b * 64 * HWSZ;

#pragma unroll 1
    for (int k = 0; k < 9; k++) {
        const float4 oyv = *(const float4*)&off[((b * 18 + 2 * k) * HH + y) * WW + xb];
        const float4 oxv = *(const float4*)&off[((b * 18 + 2 * k + 1) * HH + y) * WW + xb];
        const float4 mv  = *(const float4*)&msk[((b * 9 + k) * HH + y) * WW + xb];
        const int dky = k / 3 - 1;
        const int dkx = k % 3 - 1;
        float oys[4] = {oyv.x, oyv.y, oyv.z, oyv.w};
        float oxs[4] = {oxv.x, oxv.y, oxv.z, oxv.w};
        float ms[4]  = {mv.x, mv.y, mv.z, mv.w};

        float cw[4][4];
        int   cidx[4][4];
#pragma unroll
        for (int p = 0; p < 4; p++) {
            float py = (float)(y + dky) + oys[p];
            float px = (float)(xb + p + dkx) + oxs[p];
            float fy = floorf(py);
            float fx = floorf(px);
            float wy = py - fy;
            float wx = px - fx;
            int iy = (int)fy;
            int ix = (int)fx;
            float m = ms[p];
            float wcor[4];
            wcor[0] = (1.f - wy) * (1.f - wx) * m;
            wcor[1] = (1.f - wy) * wx * m;
            wcor[2] = wy * (1.f - wx) * m;
            wcor[3] = wy * wx * m;
            const int dys[4] = {0, 0, 1, 1};
            const int dxs[4] = {0, 1, 0, 1};
#pragma unroll
            for (int q = 0; q < 4; q++) {
                int yy = iy + dys[q];
                int xx = ix + dxs[q];
                bool valid = (yy >= 0) && (yy < HH) && (xx >= 0) && (xx < WW);
                cw[p][q] = valid ? wcor[q] : 0.f;
                int yc = min(max(yy, 0), HH - 1);
                int xc = min(max(xx, 0), WW - 1);
                cidx[p][q] = yc * WW + xc;
            }
        }

#pragma unroll 2
        for (int c = 0; c < 64; c++) {
            const float* bp = xbase + c * HWSZ;
            float samp[4];
#pragma unroll
            for (int p = 0; p < 4; p++) {
                samp[p] = cw[p][0] * __ldg(bp + cidx[p][0])
                        + cw[p][1] * __ldg(bp + cidx[p][1])
                        + cw[p][2] * __ldg(bp + cidx[p][2])
                        + cw[p][3] * __ldg(bp + cidx[p][3]);
            }
            const float* wrow = &s_w[c * 9 + k];
#pragma unroll
            for (int oc = 0; oc < 16; oc++) {
                float wv = wrow[oc * 576];
#pragma unroll
                for (int p = 0; p < 4; p++)
                    acc[oc][p] = fmaf(samp[p], wv, acc[oc][p]);
            }
        }
    }

#pragma unroll
    for (int oc = 0; oc < 16; oc++) {
        int gc = ocBase + oc;
        float bv = __ldg(&bias[gc]);
        float r[4];
#pragma unroll
        for (int p = 0; p < 4; p++) {
            float v = acc[oc][p] + bv;
            r[p] = (v >= 0.f) ? v : 0.1f * v;
        }
        float4 v4 = make_float4(r[0], r[1], r[2], r[3]);
        *(float4*)&out[((b * 64 + gc) * HH + y) * WW + xb] = v4;
    }
}

extern "C" void kernel_launch(void* const* d_in, const int* in_sizes, int n_in,
                              void* d_out, int out_size)
{
    const float* nbr   = (const float*)d_in[0];
    const float* ref   = (const float*)d_in[1];
    const float* w1    = (const float*)d_in[2];
    const float* b1    = (const float*)d_in[3];
    const float* w2    = (const float*)d_in[4];
    const float* b2    = (const float*)d_in[5];
    const float* w3    = (const float*)d_in[6];
    const float* b3    = (const float*)d_in[7];
    const float* w_off = (const float*)d_in[8];
    const float* b_off = (const float*)d_in[9];
    const float* w_dcn = (const float*)d_in[10];
    const float* b_dcn = (const float*)d_in[11];

    float* out  = (float*)d_out;
    float* feat = out;                              // [B,64,H,W]
    float* offp = out + (size_t)BB * 64 * HWSZ;     // [B,18,H,W]
    float* mskp = offp + (size_t)BB * 18 * HWSZ;    // [B,9,H,W]

    float *bufA = nullptr, *bufB = nullptr;
    cudaGetSymbolAddress((void**)&bufA, g_bufA);
    cudaGetSymbolAddress((void**)&bufB, g_bufB);

    dim3 cblk(8, 16);
    // conv1: concat(nbr, ref) 128 -> 64, lrelu
    conv3x3_k<<<dim3(4, 8, BB * 8), cblk>>>(nbr, ref, 128, w1, b1, bufA, 64, 0, nullptr, nullptr);
    // conv2: 64 -> 64, lrelu
    conv3x3_k<<<dim3(4, 8, BB * 8), cblk>>>(bufA, nullptr, 64, w2, b2, bufB, 64, 0, nullptr, nullptr);
    // conv3: 64 -> 64, lrelu
    conv3x3_k<<<dim3(4, 8, BB * 8), cblk>>>(bufB, nullptr, 64, w3, b3, bufA, 64, 0, nullptr, nullptr);
    // conv_off: 64 -> 27, split into offset (15*tanh) and mask (sigmoid), to d_out
    conv3x3_k<<<dim3(4, 8, BB * 4), cblk>>>(bufA, nullptr, 64, w_off, b_off, nullptr, 27, 1, offp, mskp);
    // DCNv2 on nbr with offsets/mask from d_out, lrelu -> feat
    dcn_k<<<dim3(32, BB * 4), dim3(32, 4)>>>(nbr, offp, mskp, w_dcn, b_dcn, feat);
}